// round 15
// baseline (speedup 1.0000x reference)
#include <cuda_runtime.h>
#include <cuda_fp16.h>
#include <math.h>
#include <float.h>
#include <stdint.h>

#define NSEQ 2048
#define DMODEL 1024
#define NHEADS 16
#define HDIM 64
#define D3 3072
#define NN ((size_t)NSEQ * NSEQ)
#define WSCALE 32.0f
#define WISCALE (1.0f / 32.0f)
#define LDS 40

__device__ float g_pq[NHEADS * NSEQ * 3];
__device__ float g_pk[NHEADS * NSEQ * 3];
__device__ float g_sqq[NHEADS * NSEQ];
__device__ float g_sqk[NHEADS * NSEQ];
__device__ float g_m[NHEADS * NSEQ];
__device__ float g_li[NHEADS * NSEQ];
__device__ float g_res[NSEQ * DMODEL];
__device__ float g_W[(size_t)NHEADS * NN];
__device__ __half g_Xh[NSEQ * DMODEL], g_Xl[NSEQ * DMODEL];
__device__ __half g_WqTh[D3 * DMODEL], g_WqTl[D3 * DMODEL];
__device__ __half g_WoTh[DMODEL * DMODEL], g_WoTl[DMODEL * DMODEL];
__device__ __half g_Ath[NSEQ * DMODEL], g_Atl[NSEQ * DMODEL];
__device__ __half g_Qh16[NHEADS * NSEQ * HDIM], g_Ql16[NHEADS * NSEQ * HDIM];
__device__ __half g_Kh16[NHEADS * NSEQ * HDIM], g_Kl16[NHEADS * NSEQ * HDIM];
__device__ __half g_VTh[NHEADS * HDIM * NSEQ], g_VTl[NHEADS * HDIM * NSEQ];

__device__ __forceinline__ float rh(float v) { return v - __half2float(__float2half_rn(v)); }
__device__ __forceinline__ uint32_t s2u(const void* p) {
    uint32_t a;
    asm("{ .reg .u64 t; cvta.to.shared.u64 t, %1; cvt.u32.u64 %0, t; }" : "=r"(a) : "l"(p));
    return a;
}
__device__ __forceinline__ void ldmA(uint32_t* r, const __half* t0, int lane) {
    uint32_t a = s2u(t0 + (lane & 15) * LDS + 8 * (lane >> 4));
    asm volatile("ldmatrix.sync.aligned.m8n8.x4.shared.b16 {%0,%1,%2,%3}, [%4];"
                 : "=r"(r[0]), "=r"(r[1]), "=r"(r[2]), "=r"(r[3]) : "r"(a));
}
__device__ __forceinline__ void ldmB(uint32_t* r, const __half* t0, int lane) {
    int l = lane & 15;
    uint32_t a = s2u(t0 + (l & 7) * LDS + 8 * (l >> 3));
    asm volatile("ldmatrix.sync.aligned.m8n8.x2.shared.b16 {%0,%1}, [%2];"
                 : "=r"(r[0]), "=r"(r[1]) : "r"(a));
}
__device__ __forceinline__ void mma16816(float* c, const uint32_t* a, const uint32_t* b) {
    asm volatile(
        "mma.sync.aligned.m16n8k16.row.col.f32.f16.f16.f32 "
        "{%0,%1,%2,%3}, {%4,%5,%6,%7}, {%8,%9}, {%0,%1,%2,%3};"
        : "+f"(c[0]), "+f"(c[1]), "+f"(c[2]), "+f"(c[3])
        : "r"(a[0]), "r"(a[1]), "r"(a[2]), "r"(a[3]), "r"(b[0]), "r"(b[1]));
}
__device__ __forceinline__ void load_tile(const __half* g, int ld, __half* s, int rows, int tid) {
    for (int i = tid; i < rows * 4; i += 256) {
        int r = i >> 2, c = i & 3;
        *(uint4*)(s + r * LDS + c * 8) = *(const uint4*)(g + (size_t)r * ld + c * 8);
    }
}
template <int NFRAG>
__device__ __forceinline__ void warp_mma(const __half* SA, const __half* SB,
                                         float (*acc)[NFRAG][4], int wm, int wn, int lane) {
#pragma unroll
    for (int kk = 0; kk < 32; kk += 16) {
        uint32_t a[4][4], b[NFRAG][2];
#pragma unroll
        for (int mi = 0; mi < 4; mi++) ldmA(a[mi], SA + (wm * 64 + mi * 16) * LDS + kk, lane);
#pragma unroll
        for (int ni = 0; ni < NFRAG; ni++)
            ldmB(b[ni], SB + (wn * (NFRAG * 8) + ni * 8) * LDS + kk, lane);
#pragma unroll
        for (int mi = 0; mi < 4; mi++)
#pragma unroll
            for (int ni = 0; ni < NFRAG; ni++) mma16816(acc[mi][ni], a[mi], b[ni]);
    }
}

// ---- pipelined GEMM core (cp.async double buffer + fused 3-product fragments) ----
__device__ __forceinline__ void cp16(uint32_t dst, const void* src) {
    asm volatile("cp.async.ca.shared.global [%0], [%1], 16;" ::"r"(dst),
                 "l"(__cvta_generic_to_global(src)));
}
__device__ __forceinline__ void cp_tile(const __half* g, int ld, __half* s, int tid) {
    for (int i = tid; i < 512; i += 256) {
        int r = i >> 2, c = i & 3;
        cp16(s2u(s + r * LDS + c * 8), g + (size_t)r * ld + c * 8);
    }
}
__device__ __forceinline__ void warp_mma3(const __half* st, float (*acc)[4][4], int wm, int wn,
                                          int lane) {
    const __half* SA0 = st;
    const __half* SA1 = st + 5120;
    const __half* SB0 = st + 10240;
    const __half* SB1 = st + 15360;
#pragma unroll
    for (int kk = 0; kk < 32; kk += 16) {
        uint32_t a0[4][4], a1[4][4], b0[4][2], b1[4][2];
#pragma unroll
        for (int mi = 0; mi < 4; mi++) {
            ldmA(a0[mi], SA0 + (wm * 64 + mi * 16) * LDS + kk, lane);
            ldmA(a1[mi], SA1 + (wm * 64 + mi * 16) * LDS + kk, lane);
        }
#pragma unroll
        for (int ni = 0; ni < 4; ni++) {
            ldmB(b0[ni], SB0 + (wn * 32 + ni * 8) * LDS + kk, lane);
            ldmB(b1[ni], SB1 + (wn * 32 + ni * 8) * LDS + kk, lane);
        }
#pragma unroll
        for (int mi = 0; mi < 4; mi++)
#pragma unroll
            for (int ni = 0; ni < 4; ni++) {
                mma16816(acc[mi][ni], a0[mi], b0[ni]);
                mma16816(acc[mi][ni], a0[mi], b1[ni]);
                mma16816(acc[mi][ni], a1[mi], b0[ni]);
            }
    }
}
__device__ __forceinline__ void gemm_pipe(const __half* Ah, const __half* Al, const __half* Bh,
                                          const __half* Bl, int K, __half* sm,
                                          float (*acc)[4][4], int tid, int wm, int wn, int lane) {
    const int nk = K >> 5;
    cp_tile(Ah, K, sm, tid);
    cp_tile(Al, K, sm + 5120, tid);
    cp_tile(Bh, K, sm + 10240, tid);
    cp_tile(Bl, K, sm + 15360, tid);
    asm volatile("cp.async.commit_group;");
    for (int it = 0; it < nk; it++) {
        __half* cur = sm + (it & 1) * 20480;
        __half* nxt = sm + ((it + 1) & 1) * 20480;
        if (it + 1 < nk) {
            const int ko = (it + 1) * 32;
            cp_tile(Ah + ko, K, nxt, tid);
            cp_tile(Al + ko, K, nxt + 5120, tid);
            cp_tile(Bh + ko, K, nxt + 10240, tid);
            cp_tile(Bl + ko, K, nxt + 15360, tid);
            asm volatile("cp.async.commit_group;");
            asm volatile("cp.async.wait_group 1;");
        } else {
            asm volatile("cp.async.wait_group 0;");
        }
        __syncthreads();
        warp_mma3(cur, acc, wm, wn, lane);
        __syncthreads();
    }
}
#define GEMM_SMEM 81920

// ---- prep ----
__global__ void split_x(const float* __restrict__ x) {
    int i = blockIdx.x * 256 + threadIdx.x;
    float v = x[i];
    g_Xh[i] = __float2half_rn(v);
    g_Xl[i] = __float2half_rn(rh(v));
}
__global__ void tsplit_wq(const float* __restrict__ in) {
    __shared__ float t[32][33];
    int c0 = blockIdx.x * 32, r0 = blockIdx.y * 32, tx = threadIdx.x, ty = threadIdx.y;
#pragma unroll
    for (int i = 0; i < 4; i++) t[ty + 8 * i][tx] = in[(size_t)(r0 + ty + 8 * i) * D3 + c0 + tx];
    __syncthreads();
#pragma unroll
    for (int i = 0; i < 4; i++) {
        float v = t[tx][ty + 8 * i] * WSCALE;
        size_t o = (size_t)(c0 + ty + 8 * i) * DMODEL + r0 + tx;
        g_WqTh[o] = __float2half_rn(v);
        g_WqTl[o] = __float2half_rn(rh(v));
    }
}
__global__ void tsplit_wo(const float* __restrict__ in) {
    __shared__ float t[32][33];
    int c0 = blockIdx.x * 32, r0 = blockIdx.y * 32, tx = threadIdx.x, ty = threadIdx.y;
#pragma unroll
    for (int i = 0; i < 4; i++)
        t[ty + 8 * i][tx] = in[(size_t)(r0 + ty + 8 * i) * DMODEL + c0 + tx];
    __syncthreads();
#pragma unroll
    for (int i = 0; i < 4; i++) {
        float v = t[tx][ty + 8 * i] * WSCALE;
        size_t o = (size_t)(c0 + ty + 8 * i) * DMODEL + r0 + tx;
        g_WoTh[o] = __float2half_rn(v);
        g_WoTl[o] = __float2half_rn(rh(v));
    }
}

// ---- HMMA QKV GEMM (pipelined) ----
__global__ __launch_bounds__(256) void hmma_qkv(const float* __restrict__ bqkv) {
    extern __shared__ __half gsm[];
    int tid = threadIdx.x, wid = tid >> 5, lane = tid & 31;
    int wm = wid >> 2, wn = wid & 3, g = lane >> 2, tg = lane & 3;
    int m0 = blockIdx.y * 128, n0 = blockIdx.x * 128;
    float acc[4][4][4] = {};
    gemm_pipe(g_Xh + (size_t)m0 * DMODEL, g_Xl + (size_t)m0 * DMODEL,
              g_WqTh + (size_t)n0 * DMODEL, g_WqTl + (size_t)n0 * DMODEL, DMODEL, gsm, acc, tid,
              wm, wn, lane);
#pragma unroll
    for (int mi = 0; mi < 4; mi++)
#pragma unroll
        for (int ni = 0; ni < 4; ni++)
#pragma unroll
            for (int rs = 0; rs < 2; rs++) {
                int row = m0 + wm * 64 + mi * 16 + g + rs * 8;
                int col = n0 + wn * 32 + ni * 8 + 2 * tg;
                float v0 = acc[mi][ni][rs * 2] * WISCALE + bqkv[col];
                float v1 = acc[mi][ni][rs * 2 + 1] * WISCALE + bqkv[col + 1];
                int which = col >> 10, hh = (col >> 6) & 15, d = col & 63;
                if (which == 2) {
                    size_t b = (size_t)hh * HDIM * NSEQ;
                    g_VTh[b + (size_t)d * NSEQ + row] = __float2half_rn(v0);
                    g_VTh[b + (size_t)(d + 1) * NSEQ + row] = __float2half_rn(v1);
                    g_VTl[b + (size_t)d * NSEQ + row] = __float2half_rn(rh(v0));
                    g_VTl[b + (size_t)(d + 1) * NSEQ + row] = __float2half_rn(rh(v1));
                } else {
                    __half* dh = (which == 0) ? g_Qh16 : g_Kh16;
                    __half* dl = (which == 0) ? g_Ql16 : g_Kl16;
                    size_t off = ((size_t)hh * NSEQ + row) * HDIM + d;
                    *(__half2*)(dh + off) = __floats2half2_rn(v0, v1);
                    *(__half2*)(dl + off) = __floats2half2_rn(rh(v0), rh(v1));
                }
            }
}

// ---- HMMA out-proj (pipelined) ----
__global__ __launch_bounds__(256) void hmma_out(const float* __restrict__ bo,
                                                const float* __restrict__ x) {
    extern __shared__ __half gsm[];
    int tid = threadIdx.x, wid = tid >> 5, lane = tid & 31;
    int wm = wid >> 2, wn = wid & 3, g = lane >> 2, tg = lane & 3;
    int m0 = blockIdx.y * 128, n0 = blockIdx.x * 128;
    float acc[4][4][4] = {};
    gemm_pipe(g_Ath + (size_t)m0 * DMODEL, g_Atl + (size_t)m0 * DMODEL,
              g_WoTh + (size_t)n0 * DMODEL, g_WoTl + (size_t)n0 * DMODEL, DMODEL, gsm, acc, tid,
              wm, wn, lane);
#pragma unroll
    for (int mi = 0; mi < 4; mi++)
#pragma unroll
        for (int ni = 0; ni < 4; ni++)
#pragma unroll
            for (int rs = 0; rs < 2; rs++) {
                int row = m0 + wm * 64 + mi * 16 + g + rs * 8;
                int col = n0 + wn * 32 + ni * 8 + 2 * tg;
                size_t off = (size_t)row * DMODEL + col;
                g_res[off] = acc[mi][ni][rs * 2] * WISCALE + bo[col] + x[off];
                g_res[off + 1] = acc[mi][ni][rs * 2 + 1] * WISCALE + bo[col + 1] + x[off + 1];
            }
}

// ---- point projections: 8 tokens/block, W amortized ----
__global__ __launch_bounds__(256) void point_proj_kernel(const float* __restrict__ x,
                                                         const float* __restrict__ Wpq,
                                                         const float* __restrict__ bpq,
                                                         const float* __restrict__ Wpk,
                                                         const float* __restrict__ bpk) {
    __shared__ float xs[8][DMODEL];
    __shared__ float outs[2][8][48];
    int n0 = blockIdx.x * 8;
    for (int i = threadIdx.x; i < 8 * DMODEL; i += 256)
        xs[i >> 10][i & 1023] = x[(size_t)n0 * DMODEL + i];
    __syncthreads();
    int t = threadIdx.x;
    if (t < 96) {
        bool isq = t < 48;
        int c = isq ? t : t - 48;
        const float* W = isq ? Wpq : Wpk;
        float b = isq ? bpq[c] : bpk[c];
        float s[8];
#pragma unroll
        for (int j = 0; j < 8; j++) s[j] = b;
        for (int k = 0; k < DMODEL; k++) {
            float w = W[k * 48 + c];
#pragma unroll
            for (int j = 0; j < 8; j++) s[j] = fmaf(xs[j][k], w, s[j]);
        }
        int h = c / 3, comp = c % 3;
        float* dst = isq ? g_pq : g_pk;
#pragma unroll
        for (int j = 0; j < 8; j++) {
            dst[((size_t)h * NSEQ + n0 + j) * 3 + comp] = s[j];
            outs[isq ? 0 : 1][j][c] = s[j];
        }
    }
    __syncthreads();
    {
        int kind = t >> 7, j = (t >> 4) & 7, h = t & 15;
        const float* s = outs[kind][j];
        float a = s[h * 3], b2 = s[h * 3 + 1], cc = s[h * 3 + 2];
        (kind == 0 ? g_sqq : g_sqk)[(size_t)h * NSEQ + n0 + j] = a * a + b2 * b2 + cc * cc;
    }
}

// ---- flash attention (verbatim R13, passing) ----
#define FL_SMEM (163840 + 9216)
__global__ __launch_bounds__(256) void flash_hmma(const unsigned char* __restrict__ mask) {
    extern __shared__ __half hsm[];
    __half* QH = hsm;
    __half* QL = hsm + 10240;
    __half* KH = hsm + 20480;
    __half* KL = hsm + 30720;
    __half* PS = hsm + 40960;
    __half* VTH = hsm + 61440;
    __half* VTL = hsm + 71680;
    float* fsm = (float*)(hsm + 81920);
    float* qp = fsm;
    float* kp = fsm + 512;
    float* kms = fsm + 1024;
    float* red = fsm + 1152;
    float* s_m = fsm + 1664;
    float* s_l = fsm + 1792;
    float* s_mn = fsm + 1920;
    float* s_al = fsm + 2048;
    float* s_li = fsm + 2176;

    const int h = blockIdx.y, q0 = blockIdx.x * 128;
    const int tid = threadIdx.x, wid = tid >> 5, lane = tid & 31;
    const int wm = wid >> 2, wn = wid & 3, g = lane >> 2, tg = lane & 3;

    for (int c = 0; c < 2; c++) {
        load_tile(g_Qh16 + ((size_t)(h * NSEQ + q0)) * HDIM + c * 32, HDIM, QH + c * 5120, 128, tid);
        load_tile(g_Ql16 + ((size_t)(h * NSEQ + q0)) * HDIM + c * 32, HDIM, QL + c * 5120, 128, tid);
    }
    if (tid < 128) {
        int n = q0 + tid;
        const float* p = g_pq + ((size_t)h * NSEQ + n) * 3;
        qp[tid * 4] = p[0];
        qp[tid * 4 + 1] = p[1];
        qp[tid * 4 + 2] = p[2];
        qp[tid * 4 + 3] = g_sqq[(size_t)h * NSEQ + n];
        s_m[tid] = -INFINITY;
        s_l[tid] = 0.f;
    }
    float acc_o[4][2][4] = {};

    for (int m0 = 0; m0 < NSEQ; m0 += 128) {
        __syncthreads();
        for (int c = 0; c < 2; c++) {
            load_tile(g_Kh16 + ((size_t)(h * NSEQ + m0)) * HDIM + c * 32, HDIM, KH + c * 5120, 128, tid);
            load_tile(g_Kl16 + ((size_t)(h * NSEQ + m0)) * HDIM + c * 32, HDIM, KL + c * 5120, 128, tid);
        }
        for (int c = 0; c < 4; c++) {
            load_tile(g_VTh + (size_t)h * HDIM * NSEQ + m0 + c * 32, NSEQ, VTH + c * 2560, 64, tid);
            load_tile(g_VTl + (size_t)h * HDIM * NSEQ + m0 + c * 32, NSEQ, VTL + c * 2560, 64, tid);
        }
        if (tid < 128) {
            int m = m0 + tid;
            const float* p = g_pk + ((size_t)h * NSEQ + m) * 3;
            kp[tid * 4] = p[0];
            kp[tid * 4 + 1] = p[1];
            kp[tid * 4 + 2] = p[2];
            kp[tid * 4 + 3] = g_sqk[(size_t)h * NSEQ + m];
            kms[tid] = mask[m] ? 1.f : 0.f;
        }
        __syncthreads();

        float acc_s[4][4][4] = {};
        for (int c = 0; c < 2; c++) {
            warp_mma<4>(QH + c * 5120, KH + c * 5120, acc_s, wm, wn, lane);
            warp_mma<4>(QH + c * 5120, KL + c * 5120, acc_s, wm, wn, lane);
            warp_mma<4>(QL + c * 5120, KH + c * 5120, acc_s, wm, wn, lane);
        }
#pragma unroll
        for (int mi = 0; mi < 4; mi++)
#pragma unroll
            for (int rs = 0; rs < 2; rs++) {
                int rl = wm * 64 + mi * 16 + g + rs * 8;
                float4 q4 = *(float4*)(qp + rl * 4);
                float rmax = -INFINITY;
#pragma unroll
                for (int ni = 0; ni < 4; ni++) {
                    int cl = wn * 32 + ni * 8 + 2 * tg;
                    float4 k0v = *(float4*)(kp + cl * 4);
                    float4 k1v = *(float4*)(kp + cl * 4 + 4);
                    float s0 = fmaf(0.125f, acc_s[mi][ni][rs * 2],
                                    q4.w + k0v.w - 2.f * (q4.x * k0v.x + q4.y * k0v.y + q4.z * k0v.z));
                    float s1 = fmaf(0.125f, acc_s[mi][ni][rs * 2 + 1],
                                    q4.w + k1v.w - 2.f * (q4.x * k1v.x + q4.y * k1v.y + q4.z * k1v.z));
                    if (kms[cl] != 0.f) s0 = -INFINITY;
                    if (kms[cl + 1] != 0.f) s1 = -INFINITY;
                    acc_s[mi][ni][rs * 2] = s0;
                    acc_s[mi][ni][rs * 2 + 1] = s1;
                    rmax = fmaxf(rmax, fmaxf(s0, s1));
                }
                rmax = fmaxf(rmax, __shfl_xor_sync(~0u, rmax, 1));
                rmax = fmaxf(rmax, __shfl_xor_sync(~0u, rmax, 2));
                if (tg == 0) red[rl * 4 + wn] = rmax;
            }
        __syncthreads();
        if (tid < 128) {
            float mo = s_m[tid];
            float mn = fmaxf(mo, fmaxf(fmaxf(red[tid * 4], red[tid * 4 + 1]),
                                       fmaxf(red[tid * 4 + 2], red[tid * 4 + 3])));
            s_mn[tid] = mn;
            s_al[tid] = (mo == -INFINITY) ? 0.f : __expf(mo - mn);
            s_m[tid] = mn;
        }
        __syncthreads();
#pragma unroll
        for (int mi = 0; mi < 4; mi++)
#pragma unroll
            for (int rs = 0; rs < 2; rs++) {
                int rl = wm * 64 + mi * 16 + g + rs * 8;
                float mn = s_mn[rl];
                float* Wr = g_W + ((size_t)h * NSEQ + q0 + rl) * NSEQ + m0;
                float rsum = 0.f;
#pragma unroll
                for (int ni = 0; ni < 4; ni++) {
                    int cl = wn * 32 + ni * 8 + 2 * tg;
                    float s0 = acc_s[mi][ni][rs * 2], s1 = acc_s[mi][ni][rs * 2 + 1];
                    *(float2*)(Wr + cl) = make_float2(s0, s1);
                    float p0 = (mn == -INFINITY) ? 0.f : __expf(s0 - mn);
                    float p1 = (mn == -INFINITY) ? 0.f : __expf(s1 - mn);
                    *(__half2*)(PS + wn * 5120 + rl * LDS + ni * 8 + 2 * tg) =
                        __floats2half2_rn(p0, p1);
                    rsum += p0 + p1;
                }
                rsum += __shfl_xor_sync(~0u, rsum, 1);
                rsum += __shfl_xor_sync(~0u, rsum, 2);
                if (tg == 0) red[rl * 4 + wn] = rsum;
            }
        __syncthreads();
        if (tid < 128) {
            float l = s_l[tid] * s_al[tid];
            l += red[tid * 4] + red[tid * 4 + 1] + red[tid * 4 + 2] + red[tid * 4 + 3];
            s_l[tid] = l;
        }
#pragma unroll
        for (int mi = 0; mi < 4; mi++)
#pragma unroll
            for (int rs = 0; rs < 2; rs++) {
                int rl = wm * 64 + mi * 16 + g + rs * 8;
                float al = s_al[rl];
#pragma unroll
                for (int ni = 0; ni < 2; ni++) {
                    acc_o[mi][ni][rs * 2] *= al;
                    acc_o[mi][ni][rs * 2 + 1] *= al;
                }
            }
        for (int c = 0; c < 4; c++) {
            warp_mma<2>(PS + c * 5120, VTH + c * 2560, acc_o, wm, wn, lane);
            warp_mma<2>(PS + c * 5120, VTL + c * 2560, acc_o, wm, wn, lane);
        }
    }
    __syncthreads();
    if (tid < 128) {
        float l = s_l[tid];
        float li = (l > 0.f) ? 1.f / l : 0.f;
        s_li[tid] = li;
        g_m[(size_t)h * NSEQ + q0 + tid] = s_m[tid];
        g_li[(size_t)h * NSEQ + q0 + tid] = li;
    }
    __syncthreads();
#pragma unroll
    for (int mi = 0; mi < 4; mi++)
#pragma unroll
        for (int rs = 0; rs < 2; rs++) {
            int rl = wm * 64 + mi * 16 + g + rs * 8;
            float li = s_li[rl];
            int row = q0 + rl;
#pragma unroll
            for (int ni = 0; ni < 2; ni++) {
                int d = wn * 16 + ni * 8 + 2 * tg;
                float v0 = acc_o[mi][ni][rs * 2] * li;
                float v1 = acc_o[mi][ni][rs * 2 + 1] * li;
                size_t off = (size_t)row * DMODEL + h * HDIM + d;
                *(__half2*)(g_Ath + off) = __floats2half2_rn(v0, v1);
                *(__half2*)(g_Atl + off) = __floats2half2_rn(rh(v0), rh(v1));
            }
        }
}

__global__ void meanw_kernel(float* __restrict__ mw) {
    size_t base = ((size_t)blockIdx.x * 256 + threadIdx.x) * 4;
    int n = (int)(base >> 11);
    float a0 = 0.f, a1 = 0.f, a2 = 0.f, a3 = 0.f;
#pragma unroll
    for (int h = 0; h < NHEADS; h++) {
        float m = g_m[(size_t)h * NSEQ + n];
        float li = g_li[(size_t)h * NSEQ + n];
        float4 s4 = *(const float4*)(g_W + (size_t)h * NN + base);
        if (li > 0.f) {
            a0 += __expf(s4.x - m) * li;
            a1 += __expf(s4.y - m) * li;
            a2 += __expf(s4.z - m) * li;
            a3 += __expf(s4.w - m) * li;
        }
    }
    const float iv = 1.f / NHEADS;
    *(float4*)(mw + base) = make_float4(a0 * iv, a1 * iv, a2 * iv, a3 * iv);
}

__global__ void ln_kernel(const float* __restrict__ gamma, const float* __restrict__ beta,
                          float* __restrict__ out) {
    const int n = blockIdx.x, tid = threadIdx.x;
    __shared__ float sr[256];
    __shared__ float s_mu, s_rs;
    const float* r = g_res + (size_t)n * DMODEL;
    float v[4], s = 0.f;
#pragma unroll
    for (int k = 0; k < 4; k++) {
        v[k] = r[tid + k * 256];
        s += v[k];
    }
    sr[tid] = s;
    __syncthreads();
    for (int o = 128; o; o >>= 1) {
        if (tid < o) sr[tid] += sr[tid + o];
        __syncthreads();
    }
    if (tid == 0) s_mu = sr[0] * (1.f / DMODEL);
    __syncthreads();
    float mu = s_mu, s2 = 0.f;
#pragma unroll
    for (int k = 0; k < 4; k++) {
        float d = v[k] - mu;
        s2 += d * d;
    }
    sr[tid] = s2;
    __syncthreads();
    for (int o = 128; o; o >>= 1) {
        if (tid < o) sr[tid] += sr[tid + o];
        __syncthreads();
    }
    if (tid == 0) s_rs = rsqrtf(sr[0] * (1.f / DMODEL) + 1e-5f);
    __syncthreads();
    float rs = s_rs;
#pragma unroll
    for (int k = 0; k < 4; k++) {
        int c = tid + k * 256;
        out[(size_t)n * DMODEL + c] = (v[k] - mu) * rs * gamma[c] + beta[c];
    }
}

extern "C" void kernel_launch(void* const* d_in, const int* in_sizes, int n_in, void* d_out,
                              int out_size) {
    const float* x = (const float*)d_in[0];
    const unsigned char* mask = (const unsigned char*)d_in[2];
    const float* Wqkv = (const float*)d_in[3];
    const float* bqkv = (const float*)d_in[4];
    const float* Wpq = (const float*)d_in[5];
    const float* bpq = (const float*)d_in[6];
    const float* Wpk = (const float*)d_in[7];
    const float* bpk = (const float*)d_in[8];
    const float* Wo = (const float*)d_in[9];
    const float* bo = (const float*)d_in[10];
    const float* gamma = (const float*)d_in[11];
    const float* beta = (const float*)d_in[12];
    float* out = (float*)d_out;
    float* meanw = out + (size_t)NSEQ * DMODEL;

    cudaFuncSetAttribute(flash_hmma, cudaFuncAttributeMaxDynamicSharedMemorySize, FL_SMEM);
    cudaFuncSetAttribute(hmma_qkv, cudaFuncAttributeMaxDynamicSharedMemorySize, GEMM_SMEM);
    cudaFuncSetAttribute(hmma_out, cudaFuncAttributeMaxDynamicSharedMemorySize, GEMM_SMEM);

    split_x<<<NSEQ * DMODEL / 256, 256>>>(x);
    tsplit_wq<<<dim3(D3 / 32, DMODEL / 32), dim3(32, 8)>>>(Wqkv);
    tsplit_wo<<<dim3(DMODEL / 32, DMODEL / 32), dim3(32, 8)>>>(Wo);
    hmma_qkv<<<dim3(D3 / 128, NSEQ / 128), 256, GEMM_SMEM>>>(bqkv);
    point_proj_kernel<<<NSEQ / 8, 256>>>(x, Wpq, bpq, Wpk, bpk);
    flash_hmma<<<dim3(NSEQ / 128, NHEADS), 256, FL_SMEM>>>(mask);
    meanw_kernel<<<NN / 1024, 256>>>(meanw);
    hmma_out<<<dim3(DMODEL / 128, NSEQ / 128), 256, GEMM_SMEM>>>(bo, x);
    ln_kernel<<<NSEQ, 256>>>(gamma, beta, out);
}

// round 16
// speedup vs baseline: 1.4662x; 1.4662x over previous
#include <cuda_runtime.h>
#include <cuda_fp16.h>
#include <math.h>
#include <float.h>
#include <stdint.h>

#define NSEQ 2048
#define DMODEL 1024
#define NHEADS 16
#define HDIM 64
#define D3 3072
#define NN ((size_t)NSEQ * NSEQ)
#define WSCALE 32.0f
#define WISCALE (1.0f / 32.0f)
#define LDS 40

__device__ float g_pq[NHEADS * NSEQ * 3];
__device__ float g_pk[NHEADS * NSEQ * 3];
__device__ float g_sqq[NHEADS * NSEQ];
__device__ float g_sqk[NHEADS * NSEQ];
__device__ float g_m[NHEADS * NSEQ];
__device__ float g_li[NHEADS * NSEQ];
__device__ float g_res[NSEQ * DMODEL];
__device__ float g_W[(size_t)NHEADS * NN];
__device__ __half g_Xh[NSEQ * DMODEL], g_Xl[NSEQ * DMODEL];
__device__ __half g_WqTh[D3 * DMODEL], g_WqTl[D3 * DMODEL];
__device__ __half g_WoTh[DMODEL * DMODEL], g_WoTl[DMODEL * DMODEL];
__device__ __half g_Ath[NSEQ * DMODEL], g_Atl[NSEQ * DMODEL];
__device__ __half g_Qh16[NHEADS * NSEQ * HDIM], g_Ql16[NHEADS * NSEQ * HDIM];
__device__ __half g_Kh16[NHEADS * NSEQ * HDIM], g_Kl16[NHEADS * NSEQ * HDIM];
__device__ __half g_VTh[NHEADS * HDIM * NSEQ], g_VTl[NHEADS * HDIM * NSEQ];

__device__ __forceinline__ float rh(float v) { return v - __half2float(__float2half_rn(v)); }
__device__ __forceinline__ uint32_t s2u(const void* p) {
    uint32_t a;
    asm("{ .reg .u64 t; cvta.to.shared.u64 t, %1; cvt.u32.u64 %0, t; }" : "=r"(a) : "l"(p));
    return a;
}
__device__ __forceinline__ void ldmA(uint32_t* r, const __half* t0, int lane) {
    uint32_t a = s2u(t0 + (lane & 15) * LDS + 8 * (lane >> 4));
    asm volatile("ldmatrix.sync.aligned.m8n8.x4.shared.b16 {%0,%1,%2,%3}, [%4];"
                 : "=r"(r[0]), "=r"(r[1]), "=r"(r[2]), "=r"(r[3]) : "r"(a));
}
__device__ __forceinline__ void ldmB(uint32_t* r, const __half* t0, int lane) {
    int l = lane & 15;
    uint32_t a = s2u(t0 + (l & 7) * LDS + 8 * (l >> 3));
    asm volatile("ldmatrix.sync.aligned.m8n8.x2.shared.b16 {%0,%1}, [%2];"
                 : "=r"(r[0]), "=r"(r[1]) : "r"(a));
}
__device__ __forceinline__ void mma16816(float* c, const uint32_t* a, const uint32_t* b) {
    asm volatile(
        "mma.sync.aligned.m16n8k16.row.col.f32.f16.f16.f32 "
        "{%0,%1,%2,%3}, {%4,%5,%6,%7}, {%8,%9}, {%0,%1,%2,%3};"
        : "+f"(c[0]), "+f"(c[1]), "+f"(c[2]), "+f"(c[3])
        : "r"(a[0]), "r"(a[1]), "r"(a[2]), "r"(a[3]), "r"(b[0]), "r"(b[1]));
}
__device__ __forceinline__ void load_tile(const __half* g, int ld, __half* s, int rows, int tid) {
    for (int i = tid; i < rows * 4; i += 256) {
        int r = i >> 2, c = i & 3;
        *(uint4*)(s + r * LDS + c * 8) = *(const uint4*)(g + (size_t)r * ld + c * 8);
    }
}

// fused 3-product: load A0/A1/B0/B1 fragments once, issue AhBh+AhBl+AlBh
__device__ __forceinline__ void warp_mma3n(const __half* SA0, const __half* SA1,
                                           const __half* SB0, const __half* SB1,
                                           float (*acc)[4][4], int wm, int wn, int lane) {
#pragma unroll
    for (int kk = 0; kk < 32; kk += 16) {
        uint32_t a0[4][4], a1[4][4], b0[4][2], b1[4][2];
#pragma unroll
        for (int mi = 0; mi < 4; mi++) {
            ldmA(a0[mi], SA0 + (wm * 64 + mi * 16) * LDS + kk, lane);
            ldmA(a1[mi], SA1 + (wm * 64 + mi * 16) * LDS + kk, lane);
        }
#pragma unroll
        for (int ni = 0; ni < 4; ni++) {
            ldmB(b0[ni], SB0 + (wn * 32 + ni * 8) * LDS + kk, lane);
            ldmB(b1[ni], SB1 + (wn * 32 + ni * 8) * LDS + kk, lane);
        }
#pragma unroll
        for (int mi = 0; mi < 4; mi++)
#pragma unroll
            for (int ni = 0; ni < 4; ni++) {
                mma16816(acc[mi][ni], a0[mi], b0[ni]);
                mma16816(acc[mi][ni], a0[mi], b1[ni]);
                mma16816(acc[mi][ni], a1[mi], b0[ni]);
            }
    }
}
// fused 2-product for PV: A shared, B hi+lo
__device__ __forceinline__ void warp_mma2n(const __half* SA, const __half* SB0,
                                           const __half* SB1, float (*acc)[2][4], int wm, int wn,
                                           int lane) {
#pragma unroll
    for (int kk = 0; kk < 32; kk += 16) {
        uint32_t a[4][4], b0[2][2], b1[2][2];
#pragma unroll
        for (int mi = 0; mi < 4; mi++) ldmA(a[mi], SA + (wm * 64 + mi * 16) * LDS + kk, lane);
#pragma unroll
        for (int ni = 0; ni < 2; ni++) {
            ldmB(b0[ni], SB0 + (wn * 16 + ni * 8) * LDS + kk, lane);
            ldmB(b1[ni], SB1 + (wn * 16 + ni * 8) * LDS + kk, lane);
        }
#pragma unroll
        for (int mi = 0; mi < 4; mi++)
#pragma unroll
            for (int ni = 0; ni < 2; ni++) {
                mma16816(acc[mi][ni], a[mi], b0[ni]);
                mma16816(acc[mi][ni], a[mi], b1[ni]);
            }
    }
}

// ---- pipelined GEMM core ----
__device__ __forceinline__ void cp16(uint32_t dst, const void* src) {
    asm volatile("cp.async.ca.shared.global [%0], [%1], 16;" ::"r"(dst),
                 "l"(__cvta_generic_to_global(src)));
}
__device__ __forceinline__ void cp_tile(const __half* g, int ld, __half* s, int tid) {
    for (int i = tid; i < 512; i += 256) {
        int r = i >> 2, c = i & 3;
        cp16(s2u(s + r * LDS + c * 8), g + (size_t)r * ld + c * 8);
    }
}
__device__ __forceinline__ void gemm_pipe(const __half* Ah, const __half* Al, const __half* Bh,
                                          const __half* Bl, int K, __half* sm,
                                          float (*acc)[4][4], int tid, int wm, int wn, int lane) {
    const int nk = K >> 5;
    cp_tile(Ah, K, sm, tid);
    cp_tile(Al, K, sm + 5120, tid);
    cp_tile(Bh, K, sm + 10240, tid);
    cp_tile(Bl, K, sm + 15360, tid);
    asm volatile("cp.async.commit_group;");
    for (int it = 0; it < nk; it++) {
        __half* cur = sm + (it & 1) * 20480;
        __half* nxt = sm + ((it + 1) & 1) * 20480;
        if (it + 1 < nk) {
            const int ko = (it + 1) * 32;
            cp_tile(Ah + ko, K, nxt, tid);
            cp_tile(Al + ko, K, nxt + 5120, tid);
            cp_tile(Bh + ko, K, nxt + 10240, tid);
            cp_tile(Bl + ko, K, nxt + 15360, tid);
            asm volatile("cp.async.commit_group;");
            asm volatile("cp.async.wait_group 1;");
        } else {
            asm volatile("cp.async.wait_group 0;");
        }
        __syncthreads();
        warp_mma3n(cur, cur + 5120, cur + 10240, cur + 15360, acc, wm, wn, lane);
        __syncthreads();
    }
}
#define GEMM_SMEM 81920

// ---- prep ----
__global__ void split_x(const float* __restrict__ x) {
    int i = blockIdx.x * 256 + threadIdx.x;
    float v = x[i];
    g_Xh[i] = __float2half_rn(v);
    g_Xl[i] = __float2half_rn(rh(v));
}
__global__ void tsplit_wq(const float* __restrict__ in) {
    __shared__ float t[32][33];
    int c0 = blockIdx.x * 32, r0 = blockIdx.y * 32, tx = threadIdx.x, ty = threadIdx.y;
#pragma unroll
    for (int i = 0; i < 4; i++) t[ty + 8 * i][tx] = in[(size_t)(r0 + ty + 8 * i) * D3 + c0 + tx];
    __syncthreads();
#pragma unroll
    for (int i = 0; i < 4; i++) {
        float v = t[tx][ty + 8 * i] * WSCALE;
        size_t o = (size_t)(c0 + ty + 8 * i) * DMODEL + r0 + tx;
        g_WqTh[o] = __float2half_rn(v);
        g_WqTl[o] = __float2half_rn(rh(v));
    }
}
__global__ void tsplit_wo(const float* __restrict__ in) {
    __shared__ float t[32][33];
    int c0 = blockIdx.x * 32, r0 = blockIdx.y * 32, tx = threadIdx.x, ty = threadIdx.y;
#pragma unroll
    for (int i = 0; i < 4; i++)
        t[ty + 8 * i][tx] = in[(size_t)(r0 + ty + 8 * i) * DMODEL + c0 + tx];
    __syncthreads();
#pragma unroll
    for (int i = 0; i < 4; i++) {
        float v = t[tx][ty + 8 * i] * WSCALE;
        size_t o = (size_t)(c0 + ty + 8 * i) * DMODEL + r0 + tx;
        g_WoTh[o] = __float2half_rn(v);
        g_WoTl[o] = __float2half_rn(rh(v));
    }
}

// ---- HMMA QKV GEMM ----
__global__ __launch_bounds__(256) void hmma_qkv(const float* __restrict__ bqkv) {
    extern __shared__ __half gsm[];
    int tid = threadIdx.x, wid = tid >> 5, lane = tid & 31;
    int wm = wid >> 2, wn = wid & 3, g = lane >> 2, tg = lane & 3;
    int m0 = blockIdx.y * 128, n0 = blockIdx.x * 128;
    float acc[4][4][4] = {};
    gemm_pipe(g_Xh + (size_t)m0 * DMODEL, g_Xl + (size_t)m0 * DMODEL,
              g_WqTh + (size_t)n0 * DMODEL, g_WqTl + (size_t)n0 * DMODEL, DMODEL, gsm, acc, tid,
              wm, wn, lane);
#pragma unroll
    for (int mi = 0; mi < 4; mi++)
#pragma unroll
        for (int ni = 0; ni < 4; ni++)
#pragma unroll
            for (int rs = 0; rs < 2; rs++) {
                int row = m0 + wm * 64 + mi * 16 + g + rs * 8;
                int col = n0 + wn * 32 + ni * 8 + 2 * tg;
                float v0 = acc[mi][ni][rs * 2] * WISCALE + bqkv[col];
                float v1 = acc[mi][ni][rs * 2 + 1] * WISCALE + bqkv[col + 1];
                int which = col >> 10, hh = (col >> 6) & 15, d = col & 63;
                if (which == 2) {
                    size_t b = (size_t)hh * HDIM * NSEQ;
                    g_VTh[b + (size_t)d * NSEQ + row] = __float2half_rn(v0);
                    g_VTh[b + (size_t)(d + 1) * NSEQ + row] = __float2half_rn(v1);
                    g_VTl[b + (size_t)d * NSEQ + row] = __float2half_rn(rh(v0));
                    g_VTl[b + (size_t)(d + 1) * NSEQ + row] = __float2half_rn(rh(v1));
                } else {
                    __half* dh = (which == 0) ? g_Qh16 : g_Kh16;
                    __half* dl = (which == 0) ? g_Ql16 : g_Kl16;
                    size_t off = ((size_t)hh * NSEQ + row) * HDIM + d;
                    *(__half2*)(dh + off) = __floats2half2_rn(v0, v1);
                    *(__half2*)(dl + off) = __floats2half2_rn(rh(v0), rh(v1));
                }
            }
}

// ---- HMMA out-proj ----
__global__ __launch_bounds__(256) void hmma_out(const float* __restrict__ bo,
                                                const float* __restrict__ x) {
    extern __shared__ __half gsm[];
    int tid = threadIdx.x, wid = tid >> 5, lane = tid & 31;
    int wm = wid >> 2, wn = wid & 3, g = lane >> 2, tg = lane & 3;
    int m0 = blockIdx.y * 128, n0 = blockIdx.x * 128;
    float acc[4][4][4] = {};
    gemm_pipe(g_Ath + (size_t)m0 * DMODEL, g_Atl + (size_t)m0 * DMODEL,
              g_WoTh + (size_t)n0 * DMODEL, g_WoTl + (size_t)n0 * DMODEL, DMODEL, gsm, acc, tid,
              wm, wn, lane);
#pragma unroll
    for (int mi = 0; mi < 4; mi++)
#pragma unroll
        for (int ni = 0; ni < 4; ni++)
#pragma unroll
            for (int rs = 0; rs < 2; rs++) {
                int row = m0 + wm * 64 + mi * 16 + g + rs * 8;
                int col = n0 + wn * 32 + ni * 8 + 2 * tg;
                size_t off = (size_t)row * DMODEL + col;
                g_res[off] = acc[mi][ni][rs * 2] * WISCALE + bo[col] + x[off];
                g_res[off + 1] = acc[mi][ni][rs * 2 + 1] * WISCALE + bo[col + 1] + x[off + 1];
            }
}

// ---- point projections: 16 tokens/block, 192 threads all computing ----
#define PP_SMEM 65536
__global__ __launch_bounds__(192) void point_proj_kernel(const float* __restrict__ x,
                                                         const float* __restrict__ Wpq,
                                                         const float* __restrict__ bpq,
                                                         const float* __restrict__ Wpk,
                                                         const float* __restrict__ bpk) {
    extern __shared__ float xs[];  // [16][1024]
    __shared__ float outs[2][16][48];
    const int n0 = blockIdx.x * 16;
    const int t = threadIdx.x;
    for (int i = t; i < 4096; i += 192)
        *(float4*)(xs + i * 4) = *(const float4*)(x + (size_t)n0 * DMODEL + i * 4);
    __syncthreads();
    const int half = t / 96, cc = t % 96;
    const bool isq = cc < 48;
    const int c = isq ? cc : cc - 48;
    const float* W = isq ? Wpq : Wpk;
    float s[8];
    const float b = isq ? bpq[c] : bpk[c];
#pragma unroll
    for (int j = 0; j < 8; j++) s[j] = b;
    const float* xb = xs + half * 8 * DMODEL;
#pragma unroll 4
    for (int k = 0; k < DMODEL; k++) {
        float w = W[k * 48 + c];
#pragma unroll
        for (int j = 0; j < 8; j++) s[j] = fmaf(xb[j * DMODEL + k], w, s[j]);
    }
    const int h = c / 3, comp = c % 3;
    float* dst = isq ? g_pq : g_pk;
#pragma unroll
    for (int j = 0; j < 8; j++) {
        dst[((size_t)h * NSEQ + n0 + half * 8 + j) * 3 + comp] = s[j];
        outs[isq ? 0 : 1][half * 8 + j][c] = s[j];
    }
    __syncthreads();
    for (int idx = t; idx < 512; idx += 192) {
        int kind = idx >> 8, r = idx & 255, j = r >> 4, h2 = r & 15;
        const float* ss = outs[kind][j];
        float a = ss[h2 * 3], b2 = ss[h2 * 3 + 1], c2 = ss[h2 * 3 + 2];
        (kind == 0 ? g_sqq : g_sqk)[(size_t)h2 * NSEQ + n0 + j] = a * a + b2 * b2 + c2 * c2;
    }
}

// ---- flash attention with fused-fragment HMMA ----
#define FL_SMEM (163840 + 9216)
__global__ __launch_bounds__(256) void flash_hmma(const unsigned char* __restrict__ mask) {
    extern __shared__ __half hsm[];
    __half* QH = hsm;
    __half* QL = hsm + 10240;
    __half* KH = hsm + 20480;
    __half* KL = hsm + 30720;
    __half* PS = hsm + 40960;
    __half* VTH = hsm + 61440;
    __half* VTL = hsm + 71680;
    float* fsm = (float*)(hsm + 81920);
    float* qp = fsm;
    float* kp = fsm + 512;
    float* kms = fsm + 1024;
    float* red = fsm + 1152;
    float* s_m = fsm + 1664;
    float* s_l = fsm + 1792;
    float* s_mn = fsm + 1920;
    float* s_al = fsm + 2048;
    float* s_li = fsm + 2176;

    const int h = blockIdx.y, q0 = blockIdx.x * 128;
    const int tid = threadIdx.x, wid = tid >> 5, lane = tid & 31;
    const int wm = wid >> 2, wn = wid & 3, g = lane >> 2, tg = lane & 3;

    for (int c = 0; c < 2; c++) {
        load_tile(g_Qh16 + ((size_t)(h * NSEQ + q0)) * HDIM + c * 32, HDIM, QH + c * 5120, 128, tid);
        load_tile(g_Ql16 + ((size_t)(h * NSEQ + q0)) * HDIM + c * 32, HDIM, QL + c * 5120, 128, tid);
    }
    if (tid < 128) {
        int n = q0 + tid;
        const float* p = g_pq + ((size_t)h * NSEQ + n) * 3;
        qp[tid * 4] = p[0];
        qp[tid * 4 + 1] = p[1];
        qp[tid * 4 + 2] = p[2];
        qp[tid * 4 + 3] = g_sqq[(size_t)h * NSEQ + n];
        s_m[tid] = -INFINITY;
        s_l[tid] = 0.f;
    }
    float acc_o[4][2][4] = {};

    for (int m0 = 0; m0 < NSEQ; m0 += 128) {
        __syncthreads();
        for (int c = 0; c < 2; c++) {
            load_tile(g_Kh16 + ((size_t)(h * NSEQ + m0)) * HDIM + c * 32, HDIM, KH + c * 5120, 128, tid);
            load_tile(g_Kl16 + ((size_t)(h * NSEQ + m0)) * HDIM + c * 32, HDIM, KL + c * 5120, 128, tid);
        }
        for (int c = 0; c < 4; c++) {
            load_tile(g_VTh + (size_t)h * HDIM * NSEQ + m0 + c * 32, NSEQ, VTH + c * 2560, 64, tid);
            load_tile(g_VTl + (size_t)h * HDIM * NSEQ + m0 + c * 32, NSEQ, VTL + c * 2560, 64, tid);
        }
        if (tid < 128) {
            int m = m0 + tid;
            const float* p = g_pk + ((size_t)h * NSEQ + m) * 3;
            kp[tid * 4] = p[0];
            kp[tid * 4 + 1] = p[1];
            kp[tid * 4 + 2] = p[2];
            kp[tid * 4 + 3] = g_sqk[(size_t)h * NSEQ + m];
            kms[tid] = mask[m] ? 1.f : 0.f;
        }
        __syncthreads();

        float acc_s[4][4][4] = {};
        for (int c = 0; c < 2; c++)
            warp_mma3n(QH + c * 5120, QL + c * 5120, KH + c * 5120, KL + c * 5120, acc_s, wm, wn,
                       lane);
#pragma unroll
        for (int mi = 0; mi < 4; mi++)
#pragma unroll
            for (int rs = 0; rs < 2; rs++) {
                int rl = wm * 64 + mi * 16 + g + rs * 8;
                float4 q4 = *(float4*)(qp + rl * 4);
                float rmax = -INFINITY;
#pragma unroll
                for (int ni = 0; ni < 4; ni++) {
                    int cl = wn * 32 + ni * 8 + 2 * tg;
                    float4 k0v = *(float4*)(kp + cl * 4);
                    float4 k1v = *(float4*)(kp + cl * 4 + 4);
                    float s0 = fmaf(0.125f, acc_s[mi][ni][rs * 2],
                                    q4.w + k0v.w - 2.f * (q4.x * k0v.x + q4.y * k0v.y + q4.z * k0v.z));
                    float s1 = fmaf(0.125f, acc_s[mi][ni][rs * 2 + 1],
                                    q4.w + k1v.w - 2.f * (q4.x * k1v.x + q4.y * k1v.y + q4.z * k1v.z));
                    if (kms[cl] != 0.f) s0 = -INFINITY;
                    if (kms[cl + 1] != 0.f) s1 = -INFINITY;
                    acc_s[mi][ni][rs * 2] = s0;
                    acc_s[mi][ni][rs * 2 + 1] = s1;
                    rmax = fmaxf(rmax, fmaxf(s0, s1));
                }
                rmax = fmaxf(rmax, __shfl_xor_sync(~0u, rmax, 1));
                rmax = fmaxf(rmax, __shfl_xor_sync(~0u, rmax, 2));
                if (tg == 0) red[rl * 4 + wn] = rmax;
            }
        __syncthreads();
        if (tid < 128) {
            float mo = s_m[tid];
            float mn = fmaxf(mo, fmaxf(fmaxf(red[tid * 4], red[tid * 4 + 1]),
                                       fmaxf(red[tid * 4 + 2], red[tid * 4 + 3])));
            s_mn[tid] = mn;
            s_al[tid] = (mo == -INFINITY) ? 0.f : __expf(mo - mn);
            s_m[tid] = mn;
        }
        __syncthreads();
#pragma unroll
        for (int mi = 0; mi < 4; mi++)
#pragma unroll
            for (int rs = 0; rs < 2; rs++) {
                int rl = wm * 64 + mi * 16 + g + rs * 8;
                float mn = s_mn[rl];
                float* Wr = g_W + ((size_t)h * NSEQ + q0 + rl) * NSEQ + m0;
                float rsum = 0.f;
#pragma unroll
                for (int ni = 0; ni < 4; ni++) {
                    int cl = wn * 32 + ni * 8 + 2 * tg;
                    float s0 = acc_s[mi][ni][rs * 2], s1 = acc_s[mi][ni][rs * 2 + 1];
                    *(float2*)(Wr + cl) = make_float2(s0, s1);
                    float p0 = (mn == -INFINITY) ? 0.f : __expf(s0 - mn);
                    float p1 = (mn == -INFINITY) ? 0.f : __expf(s1 - mn);
                    *(__half2*)(PS + wn * 5120 + rl * LDS + ni * 8 + 2 * tg) =
                        __floats2half2_rn(p0, p1);
                    rsum += p0 + p1;
                }
                rsum += __shfl_xor_sync(~0u, rsum, 1);
                rsum += __shfl_xor_sync(~0u, rsum, 2);
                if (tg == 0) red[rl * 4 + wn] = rsum;
            }
        __syncthreads();
        if (tid < 128) {
            float l = s_l[tid] * s_al[tid];
            l += red[tid * 4] + red[tid * 4 + 1] + red[tid * 4 + 2] + red[tid * 4 + 3];
            s_l[tid] = l;
        }
#pragma unroll
        for (int mi = 0; mi < 4; mi++)
#pragma unroll
            for (int rs = 0; rs < 2; rs++) {
                int rl = wm * 64 + mi * 16 + g + rs * 8;
                float al = s_al[rl];
#pragma unroll
                for (int ni = 0; ni < 2; ni++) {
                    acc_o[mi][ni][rs * 2] *= al;
                    acc_o[mi][ni][rs * 2 + 1] *= al;
                }
            }
        for (int c = 0; c < 4; c++)
            warp_mma2n(PS + c * 5120, VTH + c * 2560, VTL + c * 2560, acc_o, wm, wn, lane);
    }
    __syncthreads();
    if (tid < 128) {
        float l = s_l[tid];
        float li = (l > 0.f) ? 1.f / l : 0.f;
        s_li[tid] = li;
        g_m[(size_t)h * NSEQ + q0 + tid] = s_m[tid];
        g_li[(size_t)h * NSEQ + q0 + tid] = li;
    }
    __syncthreads();
#pragma unroll
    for (int mi = 0; mi < 4; mi++)
#pragma unroll
        for (int rs = 0; rs < 2; rs++) {
            int rl = wm * 64 + mi * 16 + g + rs * 8;
            float li = s_li[rl];
            int row = q0 + rl;
#pragma unroll
            for (int ni = 0; ni < 2; ni++) {
                int d = wn * 16 + ni * 8 + 2 * tg;
                float v0 = acc_o[mi][ni][rs * 2] * li;
                float v1 = acc_o[mi][ni][rs * 2 + 1] * li;
                size_t off = (size_t)row * DMODEL + h * HDIM + d;
                *(__half2*)(g_Ath + off) = __floats2half2_rn(v0, v1);
                *(__half2*)(g_Atl + off) = __floats2half2_rn(rh(v0), rh(v1));
            }
        }
}

__global__ void meanw_kernel(float* __restrict__ mw) {
    size_t base = ((size_t)blockIdx.x * 256 + threadIdx.x) * 4;
    int n = (int)(base >> 11);
    float a0 = 0.f, a1 = 0.f, a2 = 0.f, a3 = 0.f;
#pragma unroll
    for (int h = 0; h < NHEADS; h++) {
        float m = g_m[(size_t)h * NSEQ + n];
        float li = g_li[(size_t)h * NSEQ + n];
        float4 s4 = *(const float4*)(g_W + (size_t)h * NN + base);
        if (li > 0.f) {
            a0 += __expf(s4.x - m) * li;
            a1 += __expf(s4.y - m) * li;
            a2 += __expf(s4.z - m) * li;
            a3 += __expf(s4.w - m) * li;
        }
    }
    const float iv = 1.f / NHEADS;
    *(float4*)(mw + base) = make_float4(a0 * iv, a1 * iv, a2 * iv, a3 * iv);
}

__global__ void ln_kernel(const float* __restrict__ gamma, const float* __restrict__ beta,
                          float* __restrict__ out) {
    const int n = blockIdx.x, tid = threadIdx.x;
    __shared__ float sr[256];
    __shared__ float s_mu, s_rs;
    const float* r = g_res + (size_t)n * DMODEL;
    float v[4], s = 0.f;
#pragma unroll
    for (int k = 0; k < 4; k++) {
        v[k] = r[tid + k * 256];
        s += v[k];
    }
    sr[tid] = s;
    __syncthreads();
    for (int o = 128; o; o >>= 1) {
        if (tid < o) sr[tid] += sr[tid + o];
        __syncthreads();
    }
    if (tid == 0) s_mu = sr[0] * (1.f / DMODEL);
    __syncthreads();
    float mu = s_mu, s2 = 0.f;
#pragma unroll
    for (int k = 0; k < 4; k++) {
        float d = v[k] - mu;
        s2 += d * d;
    }
    sr[tid] = s2;
    __syncthreads();
    for (int o = 128; o; o >>= 1) {
        if (tid < o) sr[tid] += sr[tid + o];
        __syncthreads();
    }
    if (tid == 0) s_rs = rsqrtf(sr[0] * (1.f / DMODEL) + 1e-5f);
    __syncthreads();
    float rs = s_rs;
#pragma unroll
    for (int k = 0; k < 4; k++) {
        int c = tid + k * 256;
        out[(size_t)n * DMODEL + c] = (v[k] - mu) * rs * gamma[c] + beta[c];
    }
}

extern "C" void kernel_launch(void* const* d_in, const int* in_sizes, int n_in, void* d_out,
                              int out_size) {
    const float* x = (const float*)d_in[0];
    const unsigned char* mask = (const unsigned char*)d_in[2];
    const float* Wqkv = (const float*)d_in[3];
    const float* bqkv = (const float*)d_in[4];
    const float* Wpq = (const float*)d_in[5];
    const float* bpq = (const float*)d_in[6];
    const float* Wpk = (const float*)d_in[7];
    const float* bpk = (const float*)d_in[8];
    const float* Wo = (const float*)d_in[9];
    const float* bo = (const float*)d_in[10];
    const float* gamma = (const float*)d_in[11];
    const float* beta = (const float*)d_in[12];
    float* out = (float*)d_out;
    float* meanw = out + (size_t)NSEQ * DMODEL;

    cudaFuncSetAttribute(flash_hmma, cudaFuncAttributeMaxDynamicSharedMemorySize, FL_SMEM);
    cudaFuncSetAttribute(hmma_qkv, cudaFuncAttributeMaxDynamicSharedMemorySize, GEMM_SMEM);
    cudaFuncSetAttribute(hmma_out, cudaFuncAttributeMaxDynamicSharedMemorySize, GEMM_SMEM);
    cudaFuncSetAttribute(point_proj_kernel, cudaFuncAttributeMaxDynamicSharedMemorySize, PP_SMEM);

    split_x<<<NSEQ * DMODEL / 256, 256>>>(x);
    tsplit_wq<<<dim3(D3 / 32, DMODEL / 32), dim3(32, 8)>>>(Wqkv);
    tsplit_wo<<<dim3(DMODEL / 32, DMODEL / 32), dim3(32, 8)>>>(Wo);
    hmma_qkv<<<dim3(D3 / 128, NSEQ / 128), 256, GEMM_SMEM>>>(bqkv);
    point_proj_kernel<<<NSEQ / 16, 192, PP_SMEM>>>(x, Wpq, bpq, Wpk, bpk);
    flash_hmma<<<dim3(NSEQ / 128, NHEADS), 256, FL_SMEM>>>(mask);
    meanw_kernel<<<NN / 1024, 256>>>(meanw);
    hmma_out<<<dim3(DMODEL / 128, NSEQ / 128), 256, GEMM_SMEM>>>(bo, x);
    ln_kernel<<<NSEQ, 256>>>(gamma, beta, out);
}